// round 5
// baseline (speedup 1.0000x reference)
#include <cuda_runtime.h>
#include <math.h>

#define A_DIM 256
#define NV 20
#define D_DIM 256
#define NC 19
#define N_TOT (A_DIM * NV)          // 5120
#define INV_TEMP 10.0f              // 1 / 0.1
#define LOSS_SCALE (0.1 / 0.07)

// Scratch (no allocations allowed)
__device__ int    g_cnt[NC];    // class counts over the A anchors
__device__ int    g_opp[A_DIM]; // same-label, opposite-batch counts per anchor
__device__ double g_sum;        // loss accumulator (NaN-propagating)

// ---------------------------------------------------------------------------
// Kernel 1: per-anchor stats + zero accumulator. One block of A_DIM threads.
// ---------------------------------------------------------------------------
__global__ void prep_kernel(const int* __restrict__ labels,
                            const int* __restrict__ btch) {
    __shared__ int s_lab[A_DIM];
    __shared__ int s_b[A_DIM];
    __shared__ int s_cnt[NC];
    int t = threadIdx.x;
    if (t < NC) s_cnt[t] = 0;
    s_lab[t] = labels[t];
    s_b[t]   = btch[t];
    __syncthreads();
    atomicAdd(&s_cnt[s_lab[t]], 1);
    __syncthreads();
    if (t < NC) g_cnt[t] = s_cnt[t];

    int lab = s_lab[t], b = s_b[t];
    int opp = 0;
#pragma unroll 8
    for (int a2 = 0; a2 < A_DIM; a2++)
        opp += (s_lab[a2] == lab && s_b[a2] != b) ? 1 : 0;
    g_opp[t] = opp;
    if (t == 0) g_sum = 0.0;
}

// ---------------------------------------------------------------------------
// Per-row epilogue mimicking the reference's fp32 IEEE semantics.
// Key: if neg underflows to exact 0 (and other classes exist), the reference
// hits 0 * inf = NaN for that row -> whole loss becomes NaN -> final 0.
// ---------------------------------------------------------------------------
__device__ __forceinline__ float row_contrib(const float* acc, int r,
                                             const int* __restrict__ labels) {
    int a   = r / NV;
    int lab = __ldg(&labels[a]);

    float L[NC];
    float maxv = -INFINITY;
#pragma unroll
    for (int c = 0; c < NC; c++) {
        L[c] = acc[c] * INV_TEMP;
        if (g_cnt[c] > 0 && L[c] > maxv) maxv = L[c];
    }
    float neg = 0.0f;
    bool  other = false;
#pragma unroll
    for (int c = 0; c < NC; c++) {
        if (c != lab && g_cnt[c] > 0) {
            other = true;
            neg += (float)(NV * g_cnt[c]) * expf(L[c] - maxv);
        }
    }
    // Reference NaN path: neg_logits == 0 => log(0+0) = -inf at far columns,
    // pos_mask(0) * (+inf) = NaN, poisoning the mean.
    if (other && neg == 0.0f) return nanf("");

    float lpos = L[lab] - maxv;
    float lp   = lpos - logf(expf(lpos) + neg);
    float pc   = (float)(NV * g_opp[a]);
    return pc * lp / (pc + 1e-8f);
}

// ---------------------------------------------------------------------------
// Kernel 2: main. 8 warps/block, each warp handles 2 feature rows.
// ---------------------------------------------------------------------------
__global__ __launch_bounds__(256) void main_kernel(const float* __restrict__ feats,
                                                   const float* __restrict__ proto,
                                                   const int*   __restrict__ labels) {
    __shared__ float  s_proto[NC * D_DIM];
    __shared__ double s_acc;
    int t = threadIdx.x;
    if (t == 0) s_acc = 0.0;
#pragma unroll
    for (int i = t; i < NC * D_DIM; i += 256)
        s_proto[i] = proto[i];
    __syncthreads();

    int warp = t >> 5;
    int lane = t & 31;
    int r0 = blockIdx.x * 16 + warp * 2;   // this warp's two rows

    const float* f = feats + (size_t)r0 * D_DIM;
    float fr0[8], fr1[8];
#pragma unroll
    for (int k = 0; k < 8; k++) {
        fr0[k] = f[k * 32 + lane];
        fr1[k] = f[D_DIM + k * 32 + lane];
    }

    float acc0[NC], acc1[NC];
#pragma unroll
    for (int c = 0; c < NC; c++) { acc0[c] = 0.0f; acc1[c] = 0.0f; }

#pragma unroll
    for (int k = 0; k < 8; k++) {
#pragma unroll
        for (int c = 0; c < NC; c++) {
            float p = s_proto[c * D_DIM + k * 32 + lane];
            acc0[c] = fmaf(fr0[k], p, acc0[c]);
            acc1[c] = fmaf(fr1[k], p, acc1[c]);
        }
    }

    // Butterfly reduce each class dot across the warp (all lanes get the sum).
#pragma unroll
    for (int c = 0; c < NC; c++) {
        float v0 = acc0[c], v1 = acc1[c];
#pragma unroll
        for (int off = 16; off; off >>= 1) {
            v0 += __shfl_xor_sync(0xFFFFFFFFu, v0, off);
            v1 += __shfl_xor_sync(0xFFFFFFFFu, v1, off);
        }
        acc0[c] = v0; acc1[c] = v1;
    }

    if (lane == 0) {
        double contrib = (double)row_contrib(acc0, r0, labels)
                       + (double)row_contrib(acc1, r0 + 1, labels);
        atomicAdd(&s_acc, contrib);   // NaN propagates
    }
    __syncthreads();
    if (t == 0) atomicAdd(&g_sum, s_acc);
}

// ---------------------------------------------------------------------------
// Kernel 3: finalize scalar loss (NaN -> 0 like the reference).
// ---------------------------------------------------------------------------
__global__ void finish_kernel(float* __restrict__ out) {
    double mean = g_sum / (double)N_TOT;
    float loss  = (float)(-LOSS_SCALE * mean);
    if (isnan(loss)) loss = 0.0f;
    out[0] = loss;
}

// ---------------------------------------------------------------------------
extern "C" void kernel_launch(void* const* d_in, const int* in_sizes, int n_in,
                              void* d_out, int out_size) {
    // Bind inputs by size where unambiguous (robust to metadata ordering):
    //   feats_: 1310720, real_prototypes: 4864, labels/btch: 256 each (dict order).
    const float* feats  = 0;
    const float* proto  = 0;
    const int*   small[2] = {0, 0};
    int ns = 0;
    for (int i = 0; i < n_in; i++) {
        if (in_sizes[i] == A_DIM * NV * D_DIM)      feats = (const float*)d_in[i];
        else if (in_sizes[i] == NC * D_DIM)         proto = (const float*)d_in[i];
        else if (ns < 2)                            small[ns++] = (const int*)d_in[i];
    }
    const int* labels = small[0];
    const int* btch   = small[1];
    float* out = (float*)d_out;

    prep_kernel<<<1, A_DIM>>>(labels, btch);
    main_kernel<<<N_TOT / 16, 256>>>(feats, proto, labels);
    finish_kernel<<<1, 1>>>(out);
}

// round 6
// speedup vs baseline: 1.2262x; 1.2262x over previous
#include <cuda_runtime.h>
#include <math.h>

#define A_DIM 256
#define NV 20
#define D_DIM 256
#define NC 19
#define N_TOT (A_DIM * NV)          // 5120
#define INV_TEMP 10.0f              // 1 / 0.1
#define LOSS_SCALE (0.1 / 0.07)
#define GRID_BLKS (N_TOT / 16)      // 320 blocks, 16 rows each

// Persistent scratch (statically zero-initialized; reset by last block each launch)
__device__ double   g_sum   = 0.0;
__device__ unsigned g_count = 0u;

// ---------------------------------------------------------------------------
// Per-row epilogue reproducing the reference's fp32 IEEE semantics.
// If neg underflows to exact 0 while other classes exist, the reference hits
// 0 * inf = NaN -> mean NaN -> final loss 0. We emit NaN to match.
// ---------------------------------------------------------------------------
__device__ __forceinline__ float row_contrib(const float* acc, int lab,
                                             const int* s_cnt, int opp) {
    float L[NC];
    float maxv = -INFINITY;
#pragma unroll
    for (int c = 0; c < NC; c++) {
        L[c] = acc[c] * INV_TEMP;
        if (s_cnt[c] > 0 && L[c] > maxv) maxv = L[c];
    }
    float neg = 0.0f;
    bool  other = false;
#pragma unroll
    for (int c = 0; c < NC; c++) {
        if (c != lab && s_cnt[c] > 0) {
            other = true;
            neg += (float)(NV * s_cnt[c]) * expf(L[c] - maxv);
        }
    }
    if (other && neg == 0.0f) return nanf("");

    float lpos = L[lab] - maxv;
    float lp   = lpos - logf(expf(lpos) + neg);
    float pc   = (float)(NV * opp);
    return pc * lp / (pc + 1e-8f);
}

// ---------------------------------------------------------------------------
// Single fused kernel: per-block local stats + GEMV + epilogue + last-block
// finalize. 8 warps/block, each warp handles 2 rows -> 16 rows/block.
// ---------------------------------------------------------------------------
__global__ __launch_bounds__(256)
void fused_kernel(const float* __restrict__ feats,
                  const float* __restrict__ proto,
                  const int*   __restrict__ labels,
                  const int*   __restrict__ btch,
                  float*       __restrict__ out) {
    __shared__ float  s_proto[NC * D_DIM];
    __shared__ int    s_lab[A_DIM];
    __shared__ int    s_b[A_DIM];
    __shared__ int    s_cnt[NC];
    __shared__ int    s_opp[2];
    __shared__ double s_acc;

    int t = threadIdx.x;
    if (t == 0) s_acc = 0.0;
    if (t < NC) s_cnt[t] = 0;
    if (t < 2)  s_opp[t] = 0;
    s_lab[t] = labels[t];
    s_b[t]   = btch[t];

    // Stage prototypes (4864 floats = 1216 float4) into SMEM.
    const float4* p4  = (const float4*)proto;
    float4*       sp4 = (float4*)s_proto;
#pragma unroll
    for (int i = t; i < (NC * D_DIM) / 4; i += 256)
        sp4[i] = p4[i];
    __syncthreads();

    // Local class histogram + opposite-batch counts for this block's <=2 anchors.
    atomicAdd(&s_cnt[s_lab[t]], 1);
    int rbase = blockIdx.x * 16;
    int a0 = rbase / NV;
    int a1 = (rbase + 15) / NV;
    {
        int lab0 = s_lab[a0], b0 = s_b[a0];
        if (s_lab[t] == lab0 && s_b[t] != b0) atomicAdd(&s_opp[0], 1);
        if (a1 != a0) {
            int lab1 = s_lab[a1], b1 = s_b[a1];
            if (s_lab[t] == lab1 && s_b[t] != b1) atomicAdd(&s_opp[1], 1);
        }
    }
    __syncthreads();

    // GEMV: each warp computes 2 rows x 19 class dots.
    int warp = t >> 5;
    int lane = t & 31;
    int r0 = rbase + warp * 2;

    const float* f = feats + (size_t)r0 * D_DIM;
    float fr0[8], fr1[8];
#pragma unroll
    for (int k = 0; k < 8; k++) {
        fr0[k] = f[k * 32 + lane];
        fr1[k] = f[D_DIM + k * 32 + lane];
    }

    float acc0[NC], acc1[NC];
#pragma unroll
    for (int c = 0; c < NC; c++) { acc0[c] = 0.0f; acc1[c] = 0.0f; }

#pragma unroll
    for (int k = 0; k < 8; k++) {
#pragma unroll
        for (int c = 0; c < NC; c++) {
            float p = s_proto[c * D_DIM + k * 32 + lane];
            acc0[c] = fmaf(fr0[k], p, acc0[c]);
            acc1[c] = fmaf(fr1[k], p, acc1[c]);
        }
    }

#pragma unroll
    for (int c = 0; c < NC; c++) {
        float v0 = acc0[c], v1 = acc1[c];
#pragma unroll
        for (int off = 16; off; off >>= 1) {
            v0 += __shfl_xor_sync(0xFFFFFFFFu, v0, off);
            v1 += __shfl_xor_sync(0xFFFFFFFFu, v1, off);
        }
        acc0[c] = v0; acc1[c] = v1;
    }

    if (lane == 0) {
        int aA = r0 / NV;
        int aB = (r0 + 1) / NV;
        int oppA = (aA == a0) ? s_opp[0] : s_opp[1];
        int oppB = (aB == a0) ? s_opp[0] : s_opp[1];
        double contrib = (double)row_contrib(acc0, s_lab[aA], s_cnt, oppA)
                       + (double)row_contrib(acc1, s_lab[aB], s_cnt, oppB);
        atomicAdd(&s_acc, contrib);   // NaN propagates
    }
    __syncthreads();

    // Cross-block reduce: last block finalizes + resets for next graph replay.
    if (t == 0) {
        atomicAdd(&g_sum, s_acc);
        __threadfence();
        unsigned done = atomicAdd(&g_count, 1u);
        if (done == (unsigned)(gridDim.x - 1)) {
            double total = *((volatile double*)&g_sum);
            double mean  = total / (double)N_TOT;
            float loss   = (float)(-LOSS_SCALE * mean);
            if (isnan(loss)) loss = 0.0f;
            out[0] = loss;
            g_sum   = 0.0;     // reset for next replay
            g_count = 0u;
        }
    }
}

// ---------------------------------------------------------------------------
extern "C" void kernel_launch(void* const* d_in, const int* in_sizes, int n_in,
                              void* d_out, int out_size) {
    const float* feats  = 0;
    const float* proto  = 0;
    const int*   small[2] = {0, 0};
    int ns = 0;
    for (int i = 0; i < n_in; i++) {
        if (in_sizes[i] == A_DIM * NV * D_DIM)      feats = (const float*)d_in[i];
        else if (in_sizes[i] == NC * D_DIM)         proto = (const float*)d_in[i];
        else if (ns < 2)                            small[ns++] = (const int*)d_in[i];
    }
    const int* labels = small[0];
    const int* btch   = small[1];
    float* out = (float*)d_out;

    fused_kernel<<<GRID_BLKS, 256>>>(feats, proto, labels, btch, out);
}

// round 9
// speedup vs baseline: 1.3957x; 1.1383x over previous
#include <cuda_runtime.h>
#include <math.h>

#define A_DIM 256
#define NV 20
#define D_DIM 256
#define NC 19
#define N_TOT (A_DIM * NV)          // 5120
#define INV_TEMP 10.0f              // 1 / 0.1
#define LOSS_SCALE (0.1 / 0.07)
#define ROWS_PER_BLK 16
#define NTHREADS 128
#define GRID_BLKS (N_TOT / ROWS_PER_BLK)   // 320

// Persistent scratch (reset by last block each launch -> graph-replay safe)
__device__ double   g_sum   = 0.0;
__device__ unsigned g_count = 0u;

// Packed fp32x2 FMA (Blackwell FFMA2 — 2x fp32 FMA throughput)
__device__ __forceinline__ unsigned long long ffma2(unsigned long long a,
                                                    unsigned long long b,
                                                    unsigned long long c) {
    unsigned long long d;
    asm("fma.rn.f32x2 %0, %1, %2, %3;" : "=l"(d) : "l"(a), "l"(b), "l"(c));
    return d;
}
__device__ __forceinline__ float unpack_sum(unsigned long long v) {
    unsigned lo = (unsigned)v, hi = (unsigned)(v >> 32);
    return __uint_as_float(lo) + __uint_as_float(hi);
}

// ---------------------------------------------------------------------------
// Per-row epilogue reproducing the reference's fp32 IEEE semantics.
// If neg underflows to exact 0 while other classes exist, the reference hits
// 0 * inf = NaN -> mean NaN -> final loss 0. We emit NaN to match.
// ---------------------------------------------------------------------------
__device__ __forceinline__ float row_contrib(const float* dot, int lab,
                                             const int* s_cnt, int opp) {
    float L[NC];
    float maxv = -INFINITY;
#pragma unroll
    for (int c = 0; c < NC; c++) {
        L[c] = dot[c] * INV_TEMP;
        if (s_cnt[c] > 0 && L[c] > maxv) maxv = L[c];
    }
    float neg = 0.0f;
    bool  other = false;
#pragma unroll
    for (int c = 0; c < NC; c++) {
        if (c != lab && s_cnt[c] > 0) {
            other = true;
            neg += (float)(NV * s_cnt[c]) * expf(L[c] - maxv);
        }
    }
    if (other && neg == 0.0f) return nanf("");

    float lpos = L[lab] - maxv;
    float lp   = lpos - logf(expf(lpos) + neg);
    float pc   = (float)(NV * opp);
    return pc * lp / (pc + 1e-8f);
}

// ---------------------------------------------------------------------------
// Fused kernel: 128 threads, 8 threads per row, 16 rows per block.
// Thread (lr, q): row rbase+lr, owns float4 slots {q, q+8, ..., q+56}.
// ---------------------------------------------------------------------------
__global__ __launch_bounds__(NTHREADS)
void fused_kernel(const float* __restrict__ feats,
                  const float* __restrict__ proto,
                  const int*   __restrict__ labels,
                  const int*   __restrict__ btch,
                  float*       __restrict__ out) {
    __shared__ ulonglong2 s_proto[NC * 64];   // 19 x 256 floats, 16B vectors
    __shared__ int    s_lab[A_DIM];
    __shared__ int    s_b[A_DIM];
    __shared__ int    s_cnt[NC];
    __shared__ int    s_opp[2];
    __shared__ double s_acc;

    int t  = threadIdx.x;
    int lr = t >> 3;         // local row 0..15
    int q  = t & 7;          // k-slice 0..7
    int rbase = blockIdx.x * ROWS_PER_BLK;
    int r  = rbase + lr;

    // Kick off this thread's feats loads first (8 x LDG.128, coalesced).
    const ulonglong2* f4 = (const ulonglong2*)(feats + (size_t)r * D_DIM);
    ulonglong2 fr[8];
#pragma unroll
    for (int kk = 0; kk < 8; kk++)
        fr[kk] = f4[kk * 8 + q];

    // Stage prototypes into SMEM (1216 x 16B).
    const ulonglong2* p4 = (const ulonglong2*)proto;
#pragma unroll
    for (int i = t; i < NC * 64; i += NTHREADS)
        s_proto[i] = p4[i];

    // Init + stage labels/batch.
    if (t == 0) s_acc = 0.0;
    if (t < NC) s_cnt[t] = 0;
    if (t < 2)  s_opp[t] = 0;
    s_lab[t]       = labels[t];
    s_lab[t + 128] = labels[t + 128];
    s_b[t]         = btch[t];
    s_b[t + 128]   = btch[t + 128];
    __syncthreads();

    // Local stats: class histogram + opposite-batch counts for <=2 anchors.
    atomicAdd(&s_cnt[s_lab[t]], 1);
    atomicAdd(&s_cnt[s_lab[t + 128]], 1);
    int a0 = rbase / NV;
    int a1 = (rbase + ROWS_PER_BLK - 1) / NV;
    {
        int lab0 = s_lab[a0], b0 = s_b[a0];
        if (s_lab[t] == lab0       && s_b[t] != b0)       atomicAdd(&s_opp[0], 1);
        if (s_lab[t + 128] == lab0 && s_b[t + 128] != b0) atomicAdd(&s_opp[0], 1);
        if (a1 != a0) {
            int lab1 = s_lab[a1], b1 = s_b[a1];
            if (s_lab[t] == lab1       && s_b[t] != b1)       atomicAdd(&s_opp[1], 1);
            if (s_lab[t + 128] == lab1 && s_b[t + 128] != b1) atomicAdd(&s_opp[1], 1);
        }
    }

    // GEMV core: 19 packed accumulators, chains interleaved 19-wide.
    unsigned long long acc[NC];
#pragma unroll
    for (int c = 0; c < NC; c++) acc[c] = 0ull;

#pragma unroll
    for (int kk = 0; kk < 8; kk++) {
        ulonglong2 f = fr[kk];
#pragma unroll
        for (int c = 0; c < NC; c++) {
            ulonglong2 p = s_proto[c * 64 + kk * 8 + q];
            acc[c] = ffma2(f.x, p.x, acc[c]);
            acc[c] = ffma2(f.y, p.y, acc[c]);
        }
    }

    // Reduce across the 8 k-slices (3 butterfly stages within 8-lane groups).
    float dot[NC];
#pragma unroll
    for (int c = 0; c < NC; c++) {
        float v = unpack_sum(acc[c]);
        v += __shfl_xor_sync(0xFFFFFFFFu, v, 1);
        v += __shfl_xor_sync(0xFFFFFFFFu, v, 2);
        v += __shfl_xor_sync(0xFFFFFFFFu, v, 4);
        dot[c] = v;
    }

    __syncthreads();   // stats ready before epilogue reads them

    // Epilogue: 16 lanes (q==0) in parallel, one row each.
    if (q == 0) {
        int a   = r / NV;
        int opp = (a == a0) ? s_opp[0] : s_opp[1];
        float contrib = row_contrib(dot, s_lab[a], s_cnt, opp);
        atomicAdd(&s_acc, (double)contrib);   // NaN propagates
    }
    __syncthreads();

    // Cross-block reduce: last block finalizes + resets for the next replay.
    if (t == 0) {
        atomicAdd(&g_sum, s_acc);
        __threadfence();
        unsigned done = atomicAdd(&g_count, 1u);
        if (done == (unsigned)(gridDim.x - 1)) {
            double total = *((volatile double*)&g_sum);
            double mean  = total / (double)N_TOT;
            float loss   = (float)(-LOSS_SCALE * mean);
            if (isnan(loss)) loss = 0.0f;
            out[0] = loss;
            g_sum   = 0.0;
            g_count = 0u;
        }
    }
}

// ---------------------------------------------------------------------------
extern "C" void kernel_launch(void* const* d_in, const int* in_sizes, int n_in,
                              void* d_out, int out_size) {
    const float* feats  = 0;
    const float* proto  = 0;
    const int*   small[2] = {0, 0};
    int ns = 0;
    for (int i = 0; i < n_in; i++) {
        if (in_sizes[i] == A_DIM * NV * D_DIM)      feats = (const float*)d_in[i];
        else if (in_sizes[i] == NC * D_DIM)         proto = (const float*)d_in[i];
        else if (ns < 2)                            small[ns++] = (const int*)d_in[i];
    }
    const int* labels = small[0];
    const int* btch   = small[1];
    float* out = (float*)d_out;

    fused_kernel<<<GRID_BLKS, NTHREADS>>>(feats, proto, labels, btch, out);
}

// round 10
// speedup vs baseline: 1.4138x; 1.0129x over previous
#include <cuda_runtime.h>
#include <math.h>

#define A_DIM 256
#define NV 20
#define D_DIM 256
#define NC 19
#define N_TOT (A_DIM * NV)          // 5120
#define INV_TEMP 10.0f              // 1 / 0.1
#define LOSS_SCALE (0.1 / 0.07)
#define ROWS_PER_BLK 40             // exactly 2 anchors
#define NTHREADS 320                // 16 threads per row-pair x 20 pairs
#define GRID_BLKS (N_TOT / ROWS_PER_BLK)   // 128 blocks -> single wave

// Persistent scratch (reset by last block each launch -> graph-replay safe)
__device__ double   g_sum   = 0.0;
__device__ unsigned g_count = 0u;

// Packed fp32x2 FMA (Blackwell FFMA2 — 2x fp32 FMA throughput)
__device__ __forceinline__ unsigned long long ffma2(unsigned long long a,
                                                    unsigned long long b,
                                                    unsigned long long c) {
    unsigned long long d;
    asm("fma.rn.f32x2 %0, %1, %2, %3;" : "=l"(d) : "l"(a), "l"(b), "l"(c));
    return d;
}
__device__ __forceinline__ float unpack_sum(unsigned long long v) {
    unsigned lo = (unsigned)v, hi = (unsigned)(v >> 32);
    return __uint_as_float(lo) + __uint_as_float(hi);
}

// ---------------------------------------------------------------------------
// Per-row epilogue reproducing the reference's fp32 IEEE semantics.
// If neg underflows to exact 0 while other classes exist, the reference hits
// 0 * inf = NaN -> mean NaN -> final loss 0. We emit NaN to match.
// ---------------------------------------------------------------------------
__device__ __forceinline__ float row_contrib(const float* L, int lab,
                                             const int* s_cnt, int opp) {
    float maxv = -INFINITY;
#pragma unroll
    for (int c = 0; c < NC; c++)
        if (s_cnt[c] > 0 && L[c] > maxv) maxv = L[c];

    float neg = 0.0f;
    bool  other = false;
#pragma unroll
    for (int c = 0; c < NC; c++) {
        if (c != lab && s_cnt[c] > 0) {
            other = true;
            neg += (float)(NV * s_cnt[c]) * expf(L[c] - maxv);
        }
    }
    if (other && neg == 0.0f) return nanf("");

    float lpos = L[lab] - maxv;
    float lp   = lpos - logf(expf(lpos) + neg);
    float pc   = (float)(NV * opp);
    return pc * lp / (pc + 1e-8f);
}

// ---------------------------------------------------------------------------
// Fused kernel: 320 threads, 16 threads per ROW-PAIR, 20 pairs = 40 rows/block.
// Thread (p, q): rows rbase+2p, rbase+2p+1; owns float4 slots {q,q+16,q+32,q+48}.
// Each proto LDS.128 feeds 4 packed FMAs (2 rows).
// ---------------------------------------------------------------------------
__global__ __launch_bounds__(NTHREADS)
void fused_kernel(const float* __restrict__ feats,
                  const float* __restrict__ proto,
                  const int*   __restrict__ labels,
                  const int*   __restrict__ btch,
                  float*       __restrict__ out) {
    __shared__ ulonglong2 s_proto[NC * 64];   // 19 x 256 floats as 16B vectors
    __shared__ int    s_lab[A_DIM];
    __shared__ int    s_cnt[NC];
    __shared__ int    s_opp[2];
    __shared__ double s_acc;

    int t = threadIdx.x;
    int p = t >> 4;          // row-pair 0..19
    int q = t & 15;          // k-slice 0..15
    int rbase = blockIdx.x * ROWS_PER_BLK;
    int r0 = rbase + 2 * p;

    // Kick off feats loads first: 2 rows x 4 float4 (coalesced LDG.128).
    const ulonglong2* fA = (const ulonglong2*)(feats + (size_t)r0 * D_DIM);
    const ulonglong2* fB = (const ulonglong2*)(feats + (size_t)(r0 + 1) * D_DIM);
    ulonglong2 ra[4], rb[4];
#pragma unroll
    for (int kk = 0; kk < 4; kk++) {
        ra[kk] = fA[kk * 16 + q];
        rb[kk] = fB[kk * 16 + q];
    }

    // Stage prototypes into SMEM (1216 x 16B).
    const ulonglong2* p4 = (const ulonglong2*)proto;
#pragma unroll
    for (int i = t; i < NC * 64; i += NTHREADS)
        s_proto[i] = p4[i];

    // Init + stats (this block covers exactly anchors a0 = 2*bid, a0+1).
    if (t == 0) s_acc = 0.0;
    if (t < NC) s_cnt[t] = 0;
    if (t < 2)  s_opp[t] = 0;
    int a0 = 2 * blockIdx.x;
    if (t < A_DIM) {
        int lab = labels[t];
        int b   = btch[t];
        s_lab[t] = lab;
        atomicAdd(&s_cnt[lab], 1);
        int lab0 = __ldg(&labels[a0]),     b0 = __ldg(&btch[a0]);
        int lab1 = __ldg(&labels[a0 + 1]), b1 = __ldg(&btch[a0 + 1]);
        if (lab == lab0 && b != b0) atomicAdd(&s_opp[0], 1);
        if (lab == lab1 && b != b1) atomicAdd(&s_opp[1], 1);
    }
    __syncthreads();   // proto + stats ready

    // GEMV core: 19 classes x 2 rows, packed accumulators (38 u64).
    unsigned long long accA[NC], accB[NC];
#pragma unroll
    for (int c = 0; c < NC; c++) { accA[c] = 0ull; accB[c] = 0ull; }

#pragma unroll
    for (int kk = 0; kk < 4; kk++) {
        ulonglong2 a = ra[kk], b = rb[kk];
#pragma unroll
        for (int c = 0; c < NC; c++) {
            ulonglong2 pv = s_proto[c * 64 + kk * 16 + q];
            accA[c] = ffma2(a.x, pv.x, accA[c]);
            accB[c] = ffma2(b.x, pv.x, accB[c]);
            accA[c] = ffma2(a.y, pv.y, accA[c]);
            accB[c] = ffma2(b.y, pv.y, accB[c]);
        }
    }

    // Reduce across the 16 k-slices (4 butterfly stages; stays within q-group).
    float LA[NC], LB[NC];
#pragma unroll
    for (int c = 0; c < NC; c++) {
        float va = unpack_sum(accA[c]);
        float vb = unpack_sum(accB[c]);
#pragma unroll
        for (int off = 1; off < 16; off <<= 1) {
            va += __shfl_xor_sync(0xFFFFFFFFu, va, off);
            vb += __shfl_xor_sync(0xFFFFFFFFu, vb, off);
        }
        LA[c] = va * INV_TEMP;
        LB[c] = vb * INV_TEMP;
    }

    // Epilogue: q==0 handles row r0, q==8 handles row r0+1 (40 lanes busy).
    if (q == 0 || q == 8) {
        int   r    = (q == 0) ? r0 : (r0 + 1);
        const float* L = (q == 0) ? LA : LB;
        int   a    = r / NV;
        int   slot = a - a0;
        float contrib = row_contrib(L, s_lab[a], s_cnt, s_opp[slot]);
        atomicAdd(&s_acc, (double)contrib);   // NaN propagates
    }
    __syncthreads();

    // Cross-block reduce: last block finalizes + resets for the next replay.
    if (t == 0) {
        atomicAdd(&g_sum, s_acc);
        __threadfence();
        unsigned done = atomicAdd(&g_count, 1u);
        if (done == (unsigned)(gridDim.x - 1)) {
            double total = *((volatile double*)&g_sum);
            double mean  = total / (double)N_TOT;
            float loss   = (float)(-LOSS_SCALE * mean);
            if (isnan(loss)) loss = 0.0f;
            out[0] = loss;
            g_sum   = 0.0;
            g_count = 0u;
        }
    }
}

// ---------------------------------------------------------------------------
extern "C" void kernel_launch(void* const* d_in, const int* in_sizes, int n_in,
                              void* d_out, int out_size) {
    const float* feats  = 0;
    const float* proto  = 0;
    const int*   small[2] = {0, 0};
    int ns = 0;
    for (int i = 0; i < n_in; i++) {
        if (in_sizes[i] == A_DIM * NV * D_DIM)      feats = (const float*)d_in[i];
        else if (in_sizes[i] == NC * D_DIM)         proto = (const float*)d_in[i];
        else if (ns < 2)                            small[ns++] = (const int*)d_in[i];
    }
    const int* labels = small[0];
    const int* btch   = small[1];
    float* out = (float*)d_out;

    fused_kernel<<<GRID_BLKS, NTHREADS>>>(feats, proto, labels, btch, out);
}

// round 14
// speedup vs baseline: 1.4449x; 1.0220x over previous
#include <cuda_runtime.h>
#include <math.h>

#define A_DIM 256
#define NV 20
#define D_DIM 256
#define NC 19
#define N_TOT (A_DIM * NV)          // 5120
#define INV_TEMP 10.0f              // 1 / 0.1
#define LOSS_SCALE (0.1 / 0.07)
#define ROWS_PER_BLK 40             // exactly 2 anchors per block
#define NTHREADS 640                // 20 warps; warp = one row-pair
#define GRID_BLKS (N_TOT / ROWS_PER_BLK)   // 128 blocks -> single wave

// Persistent scratch (reset by last block each launch -> graph-replay safe)
__device__ double   g_sum   = 0.0;
__device__ unsigned g_count = 0u;

// Packed fp32x2 FMA (Blackwell FFMA2 — 2x fp32 FMA throughput)
__device__ __forceinline__ unsigned long long ffma2(unsigned long long a,
                                                    unsigned long long b,
                                                    unsigned long long c) {
    unsigned long long d;
    asm("fma.rn.f32x2 %0, %1, %2, %3;" : "=l"(d) : "l"(a), "l"(b), "l"(c));
    return d;
}
__device__ __forceinline__ float unpack_sum(unsigned long long v) {
    unsigned lo = (unsigned)v, hi = (unsigned)(v >> 32);
    return __uint_as_float(lo) + __uint_as_float(hi);
}

// ---------------------------------------------------------------------------
// Per-row epilogue reproducing the reference's fp32 IEEE semantics.
// If neg underflows to exact 0 while other classes exist, the reference hits
// 0 * inf = NaN -> mean NaN -> final loss 0. We emit NaN to match.
// ---------------------------------------------------------------------------
__device__ __forceinline__ float row_contrib(const float* L, int lab,
                                             const int* s_cnt, int opp) {
    float maxv = -INFINITY;
#pragma unroll
    for (int c = 0; c < NC; c++)
        if (s_cnt[c] > 0 && L[c] > maxv) maxv = L[c];

    float neg = 0.0f;
    bool  other = false;
#pragma unroll
    for (int c = 0; c < NC; c++) {
        if (c != lab && s_cnt[c] > 0) {
            other = true;
            neg += (float)(NV * s_cnt[c]) * expf(L[c] - maxv);
        }
    }
    if (other && neg == 0.0f) return nanf("");

    float lpos = L[lab] - maxv;
    float lp   = lpos - logf(expf(lpos) + neg);
    float pc   = (float)(NV * opp);
    return pc * lp / (pc + 1e-8f);
}

// ---------------------------------------------------------------------------
// Fused kernel: 640 threads = 20 warps; warp w handles rows rbase+2w(+1).
// Lanes 0-15 -> row A, lanes 16-31 -> row B; lane owns 16 scalars (4 float4).
// Proto LDS addresses identical across the two halves -> crossbar broadcast.
// ---------------------------------------------------------------------------
__global__ __launch_bounds__(NTHREADS)
void fused_kernel(const float* __restrict__ feats,
                  const float* __restrict__ proto,
                  const int*   __restrict__ labels,
                  const int*   __restrict__ btch,
                  float*       __restrict__ out) {
    __shared__ ulonglong2 s_proto[NC * 64];   // 19 x 256 floats as 16B vectors
    __shared__ int   s_cnt[NC];
    __shared__ int   s_opp[2];
    __shared__ float s_wsum[20];

    int t    = threadIdx.x;
    int warp = t >> 5;
    int lane = t & 31;
    int half = lane >> 4;    // 0 = row A, 1 = row B
    int q    = lane & 15;    // slice within the row
    int rbase = blockIdx.x * ROWS_PER_BLK;
    int r     = rbase + 2 * warp + half;
    int a0    = 2 * blockIdx.x;

    // Kick off this thread's feats loads first (4 x LDG.128, coalesced).
    const ulonglong2* f4 = (const ulonglong2*)(feats + (size_t)r * D_DIM);
    ulonglong2 fr[4];
#pragma unroll
    for (int s = 0; s < 4; s++)
        fr[s] = f4[s * 16 + q];

    // Stage prototypes into SMEM (1216 x 16B over 640 threads).
    const ulonglong2* p4 = (const ulonglong2*)proto;
    for (int i = t; i < NC * 64; i += NTHREADS)
        s_proto[i] = p4[i];

    // Stats: histogram via smem atomics; opp counts via ballot+popc.
    if (t < NC) s_cnt[t] = 0;
    if (t < 2)  s_opp[t] = 0;
    __syncthreads();
    int lab0 = __ldg(&labels[a0]),     b0 = __ldg(&btch[a0]);
    int lab1 = __ldg(&labels[a0 + 1]), b1 = __ldg(&btch[a0 + 1]);
    if (t < A_DIM) {
        int lab = labels[t];
        int b   = btch[t];
        atomicAdd(&s_cnt[lab], 1);
        unsigned m0 = __ballot_sync(0xFFFFFFFFu, lab == lab0 && b != b0);
        unsigned m1 = __ballot_sync(0xFFFFFFFFu, lab == lab1 && b != b1);
        if (lane == 0) {
            if (m0) atomicAdd(&s_opp[0], (int)__popc(m0));
            if (m1) atomicAdd(&s_opp[1], (int)__popc(m1));
        }
    }
    __syncthreads();   // proto + stats ready

    // GEMV core: 19 packed accumulators per thread (one row each).
    unsigned long long acc[NC];
#pragma unroll
    for (int c = 0; c < NC; c++) acc[c] = 0ull;

#pragma unroll
    for (int s = 0; s < 4; s++) {
        ulonglong2 f = fr[s];
#pragma unroll
        for (int c = 0; c < NC; c++) {
            ulonglong2 pv = s_proto[c * 64 + s * 16 + q];
            acc[c] = ffma2(f.x, pv.x, acc[c]);
            acc[c] = ffma2(f.y, pv.y, acc[c]);
        }
    }

    // Reduce each class over this 16-lane half (4 butterfly stages; xor<16
    // keeps every exchange inside the half, so halves stay independent).
    float L[NC];
#pragma unroll
    for (int c = 0; c < NC; c++) {
        float v = unpack_sum(acc[c]);
        v += __shfl_xor_sync(0xFFFFFFFFu, v, 1);
        v += __shfl_xor_sync(0xFFFFFFFFu, v, 2);
        v += __shfl_xor_sync(0xFFFFFFFFu, v, 4);
        v += __shfl_xor_sync(0xFFFFFFFFu, v, 8);
        L[c] = v * INV_TEMP;
    }

    // Epilogue: lane 0 -> row A, lane 16 -> row B; combine pair via shfl.
    float contrib = 0.0f;
    if (q == 0) {
        int a    = r / NV;
        int slot = a - a0;
        int lab  = (slot == 0) ? lab0 : lab1;
        contrib  = row_contrib(L, lab, s_cnt, s_opp[slot]);
    }
    float cB = __shfl_down_sync(0xFFFFFFFFu, contrib, 16);
    if (lane == 0) s_wsum[warp] = contrib + cB;   // NaN propagates
    __syncthreads();

    // Block reduce (warp 0, 5-stage butterfly over padded 32) + finalize.
    if (warp == 0) {
        float v = (lane < 20) ? s_wsum[lane] : 0.0f;
        v += __shfl_xor_sync(0xFFFFFFFFu, v, 1);
        v += __shfl_xor_sync(0xFFFFFFFFu, v, 2);
        v += __shfl_xor_sync(0xFFFFFFFFu, v, 4);
        v += __shfl_xor_sync(0xFFFFFFFFu, v, 8);
        v += __shfl_xor_sync(0xFFFFFFFFu, v, 16);
        if (lane == 0) {
            atomicAdd(&g_sum, (double)v);
            __threadfence();
            unsigned done = atomicAdd(&g_count, 1u);
            if (done == (unsigned)(gridDim.x - 1)) {
                double total = *((volatile double*)&g_sum);
                double mean  = total / (double)N_TOT;
                float loss   = (float)(-LOSS_SCALE * mean);
                if (isnan(loss)) loss = 0.0f;
                out[0] = loss;
                g_sum   = 0.0;
                g_count = 0u;
            }
        }
    }
}

// ---------------------------------------------------------------------------
extern "C" void kernel_launch(void* const* d_in, const int* in_sizes, int n_in,
                              void* d_out, int out_size) {
    const float* feats  = 0;
    const float* proto  = 0;
    const int*   small[2] = {0, 0};
    int ns = 0;
    for (int i = 0; i < n_in; i++) {
        if (in_sizes[i] == A_DIM * NV * D_DIM)      feats = (const float*)d_in[i];
        else if (in_sizes[i] == NC * D_DIM)         proto = (const float*)d_in[i];
        else if (ns < 2)                            small[ns++] = (const int*)d_in[i];
    }
    const int* labels = small[0];
    const int* btch   = small[1];
    float* out = (float*)d_out;

    fused_kernel<<<GRID_BLKS, NTHREADS>>>(feats, proto, labels, btch, out);
}

// round 16
// speedup vs baseline: 1.6400x; 1.1350x over previous
#include <cuda_runtime.h>
#include <math.h>

#define A_DIM 256
#define NV 20
#define D_DIM 256
#define NC 19
#define N_TOT (A_DIM * NV)          // 5120
#define INV_TEMP 10.0f              // 1 / 0.1
#define LOSS_SCALE (0.1 / 0.07)
#define ROWS_PER_BLK 20             // exactly 1 anchor per block
#define NTHREADS 320                // 10 warps; warp = one row-pair
#define NWARPS 10
#define GRID_BLKS (N_TOT / ROWS_PER_BLK)   // 256 blocks -> 2 CTAs/SM

// Persistent scratch (reset by last block each launch -> graph-replay safe)
__device__ double   g_sum   = 0.0;
__device__ unsigned g_count = 0u;

// Packed fp32x2 FMA (Blackwell FFMA2 — 2x fp32 FMA throughput)
__device__ __forceinline__ unsigned long long ffma2(unsigned long long a,
                                                    unsigned long long b,
                                                    unsigned long long c) {
    unsigned long long d;
    asm("fma.rn.f32x2 %0, %1, %2, %3;" : "=l"(d) : "l"(a), "l"(b), "l"(c));
    return d;
}
__device__ __forceinline__ float unpack_sum(unsigned long long v) {
    unsigned lo = (unsigned)v, hi = (unsigned)(v >> 32);
    return __uint_as_float(lo) + __uint_as_float(hi);
}

// ---------------------------------------------------------------------------
// Fused kernel: 320 threads = 10 warps; warp w -> rows rbase+2w, rbase+2w+1.
// Lanes 0-15 = row A, lanes 16-31 = row B; lane owns 16 scalars (4 float4).
// Epilogue parallelized over the 16 lanes of each half.
// ---------------------------------------------------------------------------
__global__ __launch_bounds__(NTHREADS)
void fused_kernel(const float* __restrict__ feats,
                  const float* __restrict__ proto,
                  const int*   __restrict__ labels,
                  const int*   __restrict__ btch,
                  float*       __restrict__ out) {
    __shared__ ulonglong2 s_proto[NC * 64];   // 19 x 256 floats as 16B vectors
    __shared__ int   s_cnt[NC];
    __shared__ int   s_opp;
    __shared__ float s_L[NWARPS][2][NC + 1];  // transposed logits, padded
    __shared__ float s_wsum[NWARPS];

    int t    = threadIdx.x;
    int warp = t >> 5;
    int lane = t & 31;
    int half = lane >> 4;    // 0 = row A, 1 = row B
    int q    = lane & 15;    // slice / class-slot index
    int a0   = blockIdx.x;   // this block's single anchor
    int r    = a0 * ROWS_PER_BLK + 2 * warp + half;

    // Kick off this thread's feats loads first (4 x LDG.128, coalesced).
    const ulonglong2* f4 = (const ulonglong2*)(feats + (size_t)r * D_DIM);
    ulonglong2 fr[4];
#pragma unroll
    for (int s = 0; s < 4; s++)
        fr[s] = f4[s * 16 + q];

    // Stage prototypes into SMEM (1216 x 16B over 320 threads).
    const ulonglong2* p4 = (const ulonglong2*)proto;
#pragma unroll
    for (int i = t; i < NC * 64; i += NTHREADS)
        s_proto[i] = p4[i];

    if (t < NC) s_cnt[t] = 0;
    if (t == 0) s_opp = 0;
    __syncthreads();

    int lab0 = __ldg(&labels[a0]), b0 = __ldg(&btch[a0]);
    if (t < A_DIM) {                      // warps 0-7 fully active
        int lab = labels[t];
        int b   = btch[t];
        atomicAdd(&s_cnt[lab], 1);
        unsigned m0 = __ballot_sync(0xFFFFFFFFu, lab == lab0 && b != b0);
        if (lane == 0 && m0) atomicAdd(&s_opp, (int)__popc(m0));
    }
    __syncthreads();   // proto + stats ready

    // GEMV core: 19 packed accumulators per thread (one row each).
    unsigned long long acc[NC];
#pragma unroll
    for (int c = 0; c < NC; c++) acc[c] = 0ull;

#pragma unroll
    for (int s = 0; s < 4; s++) {
        ulonglong2 f = fr[s];
#pragma unroll
        for (int c = 0; c < NC; c++) {
            ulonglong2 pv = s_proto[c * 64 + s * 16 + q];
            acc[c] = ffma2(f.x, pv.x, acc[c]);
            acc[c] = ffma2(f.y, pv.y, acc[c]);
        }
    }

    // Reduce each class over this 16-lane half (xor<16 stays inside the half).
    float L[NC];
#pragma unroll
    for (int c = 0; c < NC; c++) {
        float v = unpack_sum(acc[c]);
        v += __shfl_xor_sync(0xFFFFFFFFu, v, 1);
        v += __shfl_xor_sync(0xFFFFFFFFu, v, 2);
        v += __shfl_xor_sync(0xFFFFFFFFu, v, 4);
        v += __shfl_xor_sync(0xFFFFFFFFu, v, 8);
        L[c] = v * INV_TEMP;
    }

    // Transpose L into per-warp SMEM (predicated STS, constant reg indices).
#pragma unroll
    for (int c = 0; c < 16; c++)
        if (q == c) s_L[warp][half][c] = L[c];
#pragma unroll
    for (int c = 16; c < NC; c++)
        if (q == c - 16) s_L[warp][half][c] = L[c];
    __syncwarp();

    // --- Parallel epilogue: lane q of each half owns classes {q, q+16} ---
    int   cnt0 = s_cnt[q];
    float Lq0  = s_L[warp][half][q];
    int   c1   = q + 16;
    int   cnt1 = (c1 < NC) ? s_cnt[c1] : 0;
    float Lq1  = (c1 < NC) ? s_L[warp][half][c1] : -INFINITY;

    float m = (cnt0 > 0) ? Lq0 : -INFINITY;
    if (cnt1 > 0 && Lq1 > m) m = Lq1;
#pragma unroll
    for (int off = 1; off < 16; off <<= 1)
        m = fmaxf(m, __shfl_xor_sync(0xFFFFFFFFu, m, off));

    float neg = 0.0f;
    if (cnt0 > 0 && q != lab0)
        neg += (float)(NV * cnt0) * __expf(Lq0 - m);
    if (cnt1 > 0 && c1 != lab0 && c1 < NC)
        neg += (float)(NV * cnt1) * __expf(Lq1 - m);
#pragma unroll
    for (int off = 1; off < 16; off <<= 1)
        neg += __shfl_xor_sync(0xFFFFFFFFu, neg, off);

    float contrib = 0.0f;
    if (q == 0) {
        bool other = (A_DIM - s_cnt[lab0]) > 0;
        if (other && neg == 0.0f) {
            contrib = nanf("");        // reference's 0*inf=NaN path
        } else {
            float lpos = s_L[warp][half][lab0] - m;
            float lp   = lpos - __logf(__expf(lpos) + neg);
            float pc   = (float)(NV * s_opp);
            contrib    = pc * lp / (pc + 1e-8f);
        }
    }
    float cB = __shfl_down_sync(0xFFFFFFFFu, contrib, 16);
    if (lane == 0) s_wsum[warp] = contrib + cB;   // NaN propagates
    __syncthreads();

    // Block reduce (warp 0, lanes 0-15) + cross-block finalize.
    if (warp == 0) {
        float v = (lane < NWARPS) ? s_wsum[lane] : 0.0f;
        v += __shfl_xor_sync(0xFFFFFFFFu, v, 1);
        v += __shfl_xor_sync(0xFFFFFFFFu, v, 2);
        v += __shfl_xor_sync(0xFFFFFFFFu, v, 4);
        v += __shfl_xor_sync(0xFFFFFFFFu, v, 8);
        if (lane == 0) {
            atomicAdd(&g_sum, (double)v);
            __threadfence();
            unsigned done = atomicAdd(&g_count, 1u);
            if (done == (unsigned)(gridDim.x - 1)) {
                double total = *((volatile double*)&g_sum);
                double mean  = total / (double)N_TOT;
                float loss   = (float)(-LOSS_SCALE * mean);
                if (isnan(loss)) loss = 0.0f;
                out[0] = loss;
                g_sum   = 0.0;
                g_count = 0u;
            }
        }
    }
}

// ---------------------------------------------------------------------------
extern "C" void kernel_launch(void* const* d_in, const int* in_sizes, int n_in,
                              void* d_out, int out_size) {
    const float* feats  = 0;
    const float* proto  = 0;
    const int*   small[2] = {0, 0};
    int ns = 0;
    for (int i = 0; i < n_in; i++) {
        if (in_sizes[i] == A_DIM * NV * D_DIM)      feats = (const float*)d_in[i];
        else if (in_sizes[i] == NC * D_DIM)         proto = (const float*)d_in[i];
        else if (ns < 2)                            small[ns++] = (const int*)d_in[i];
    }
    const int* labels = small[0];
    const int* btch   = small[1];
    float* out = (float*)d_out;

    fused_kernel<<<GRID_BLKS, NTHREADS>>>(feats, proto, labels, btch, out);
}